// round 11
// baseline (speedup 1.0000x reference)
#include <cuda_runtime.h>

#define BATCH 16
#define HH 512
#define WW 512
#define HWSZ (HH * WW)
#define TR 8

// ---- scratch (no allocations allowed; zero-initialized at module load) ----
// g_phase[b][0][k] = sum of de_h over all pixels in columns with col%8==k (cols 0..510)
// g_phase[b][1][k] = sum of de_v over all pixels in rows    with row%8==k (rows 0..510)
__device__ float g_phase[BATCH][2][8];
__device__ unsigned int g_done[BATCH];   // per-batch writer-completion tickets

__device__ __forceinline__ float lum1(const float* p) {
    return 0.299f * p[0] + 0.587f * p[HWSZ] + 0.114f * p[2 * HWSZ];
}
__device__ __forceinline__ float2 lum2(float2 c0, float2 c1, float2 c2) {
    float2 l;
    l.x = 0.299f * c0.x + 0.587f * c1.x + 0.114f * c2.x;
    l.y = 0.299f * c0.y + 0.587f * c1.y + 0.114f * c2.y;
    return l;
}
// clipped excess: max(|t0-t1| - |r0-r1|, 0)
__device__ __forceinline__ float dexc(float t0, float t1, float r0, float r1) {
    return fmaxf(fabsf(t0 - t1) - fabsf(r0 - r1), 0.0f);
}

// -------------------------------------------------------------------------
// Kernel 1: streaming reduction directly into PHASE BINS.
// Warp = 64-col x TR-row strip, float2 per lane (proven memory layout).
// Col contributions: lane's 2 cols have static phases (2*lane)&7, +1;
//   shfl_xor(4,8,16) sums 4-lane phase groups; lanes 0-3 -> smem bins.
// Row contributions: per-row warp-reduced dv -> smem bin (i-1)&7.
// Block flushes its 16 smem bins with 16 global atomics (all warps same b).
// grid: BATCH * 64 tiles * 8 strips = 8192 warps, 8 warps/block.
// -------------------------------------------------------------------------
__global__ __launch_bounds__(256) void jb_accum_kernel(
    const float* __restrict__ ref, const float* __restrict__ tgt)
{
    const int t     = threadIdx.x;
    const int gw    = blockIdx.x * 8 + (t >> 5);
    const int lane  = t & 31;
    const int b     = gw >> 9;            // 512 warps per batch; whole block same b
    const int rem   = gw & 511;
    const int tile  = rem >> 3;
    const int strip = rem & 7;
    const int r0    = tile * TR;          // multiple of 8
    const int c0    = strip * 64 + lane * 2;

    __shared__ float s_ph[2][8];
    if (t < 16) s_ph[t >> 3][t & 7] = 0.0f;
    __syncthreads();

    const float* rB = ref + (size_t)b * 3 * HWSZ;
    const float* tB = tgt + (size_t)b * 3 * HWSZ;

    const bool bnd_load = (lane == 31) && (strip < 7);   // col c0+2 in next strip
    const bool bnd_skip = (lane == 31) && (strip == 7);  // col 511: no right neighbor

    float2 cacc = make_float2(0.f, 0.f);
    float2 plr, plt;

    #pragma unroll 3
    for (int i = 0; i <= TR; ++i) {
        const int r = min(r0 + i, HH - 1);       // clamp phantom row (dv==0 there)
        const float* rp = rB + (size_t)r * WW + c0;
        const float* tp = tB + (size_t)r * WW + c0;
        float2 rc0 = *reinterpret_cast<const float2*>(rp);
        float2 rc1 = *reinterpret_cast<const float2*>(rp + HWSZ);
        float2 rc2 = *reinterpret_cast<const float2*>(rp + 2 * HWSZ);
        float2 tc0 = *reinterpret_cast<const float2*>(tp);
        float2 tc1 = *reinterpret_cast<const float2*>(tp + HWSZ);
        float2 tc2 = *reinterpret_cast<const float2*>(tp + 2 * HWSZ);
        float2 lr = lum2(rc0, rc1, rc2);
        float2 lt = lum2(tc0, tc1, tc2);

        if (i < TR) {
            float nr = __shfl_down_sync(0xffffffffu, lr.x, 1);
            float nt = __shfl_down_sync(0xffffffffu, lt.x, 1);
            if (bnd_load) {                  // boundary luminance (col c0+2)
                nr = lum1(rp + 2);
                nt = lum1(tp + 2);
            }
            cacc.x += dexc(lt.x, lt.y, lr.x, lr.y);
            if (!bnd_skip)
                cacc.y += dexc(lt.y, nt, lr.y, nr);
        }

        if (i > 0) {
            float dv = dexc(plt.x, lt.x, plr.x, lr.x)
                     + dexc(plt.y, lt.y, plr.y, lr.y);
            #pragma unroll
            for (int off = 16; off > 0; off >>= 1)
                dv += __shfl_down_sync(0xffffffffu, dv, off);
            if (lane == 0)
                atomicAdd(&s_ph[1][(i - 1) & 7], dv);  // row phase (r0%8==0)
        }
        plr = lr; plt = lt;
    }

    // ---- column phase reduce: sum the 4-lane groups (same (lane&3)) ----
    #pragma unroll
    for (int off = 4; off < 32; off <<= 1) {
        cacc.x += __shfl_xor_sync(0xffffffffu, cacc.x, off);
        cacc.y += __shfl_xor_sync(0xffffffffu, cacc.y, off);
    }
    if (lane < 4) {
        atomicAdd(&s_ph[0][lane * 2 + 0], cacc.x);   // phase 2*lane
        atomicAdd(&s_ph[0][lane * 2 + 1], cacc.y);   // phase 2*lane+1
    }
    __syncthreads();

    if (t < 16)
        atomicAdd(&g_phase[b][t >> 3][t & 7], s_ph[t >> 3][t & 7]);
}

// -------------------------------------------------------------------------
// Kernel 2 (decide + write): block loads its batch's 16 phase sums (64 B),
// one thread per direction runs the ratio test, then the block paints its
// 16-row x 512-col slice (32 floats / thread, 8 x STG.128).
// Last of a batch's 32 blocks (exit ticket) zeroes that batch's 16 bins.
// grid: BATCH * 32 = 512 blocks of 256 threads.
// -------------------------------------------------------------------------
__global__ __launch_bounds__(256) void jb_decide_write_kernel(float* __restrict__ out)
{
    const int b   = blockIdx.x >> 5;         // 32 blocks per batch
    const int blk = blockIdx.x & 31;         // slice index within batch
    const int t   = threadIdx.x;

    __shared__ float ph[16];
    __shared__ int   dec[4];                 // kh, bh, kv, bv
    if (t < 16) ph[t] = g_phase[b][t >> 3][t & 7];
    __syncthreads();

    if (t < 2) {
        float total = 0.0f;
        #pragma unroll
        for (int k = 0; k < 8; ++k) total += ph[t * 8 + k];
        float best_r = -1.0f;
        int   best_k = 0;
        #pragma unroll
        for (int k = 0; k < 8; ++k) {
            // phase sums are pixel sums; line mean scale = /512
            float s     = ph[t * 8 + k] * (1.0f / 512.0f);
            float tot   = total * (1.0f / 512.0f);
            float cnt   = (k < 7) ? 64.0f : 63.0f;   // 511 lines: phases 0..6 have 64
            float a_k   = s / cnt;
            float bg    = (tot - s) / (511.0f - cnt);
            float ratio = a_k / (bg + 1e-8f);
            if (ratio > best_r) { best_r = ratio; best_k = k; }  // first-max (argmax)
        }
        dec[t * 2 + 0] = best_k;
        dec[t * 2 + 1] = best_r > (1.0f / 0.35f);
    }
    __syncthreads();

    // ---- write 16 rows: 256 threads x 32 floats ----
    {
        const int kh = dec[0], bh = dec[1];
        const int kv = dec[2], bv = dec[3];
        const int row = blk * 16 + (t >> 4);     // 16 threads per row
        const int cg  = t & 15;                  // 32-col chunk
        const bool vrow = bv && ((row & 7) == kv) && (row < HH - 1);
        const bool tail = (cg == 15);            // chunk containing col 511

        float4 o[8];
        float* op = reinterpret_cast<float*>(o);
        #pragma unroll
        for (int j = 0; j < 32; ++j) {
            bool vcol = bh && ((j & 7) == kh) && !(tail && j == 31);
            op[j] = (vrow || vcol) ? 1.0f : 0.0f;
        }
        float4* dst = reinterpret_cast<float4*>(
            out + ((size_t)b * HH + row) * WW + cg * 32);
        #pragma unroll
        for (int j = 0; j < 8; ++j) dst[j] = o[j];
    }

    // ---- exit ticket: last block of this batch zeroes its 16 bins ----
    __shared__ unsigned int s_ticket;
    if (t == 0) {
        __threadfence();                     // my reads of g_phase[b] are complete
        s_ticket = atomicAdd(&g_done[b], 1u) + 1u;
    }
    __syncthreads();
    if (s_ticket == 32u) {                   // all 32 readers of batch b are done
        if (t < 16) g_phase[b][t >> 3][t & 7] = 0.0f;
        if (t == 0) { g_done[b] = 0u; __threadfence(); }
    }
}

// -------------------------------------------------------------------------
extern "C" void kernel_launch(void* const* d_in, const int* in_sizes, int n_in,
                              void* d_out, int out_size)
{
    const float* ref = (const float*)d_in[0];
    const float* tgt = (const float*)d_in[1];
    float* out = (float*)d_out;

    // 16 batches * 64 tiles * 8 strips = 8192 warps -> 1024 blocks of 8 warps
    jb_accum_kernel<<<1024, 256>>>(ref, tgt);

    // 16 batches * 32 row-slices
    jb_decide_write_kernel<<<512, 256>>>(out);
}